// round 16
// baseline (speedup 1.0000x reference)
#include <cuda_runtime.h>
#include <math.h>

#define FFT_N  4096
#define NT     256
#define PAD(i) ((i) + ((i) >> 4))
#define SMEM_E (FFT_N + (FFT_N >> 4))   // 4352 float2 = 34816 B per row buffer

__device__ __forceinline__ float2 cadd(float2 a, float2 b) { return make_float2(a.x + b.x, a.y + b.y); }
__device__ __forceinline__ float2 csub(float2 a, float2 b) { return make_float2(a.x - b.x, a.y - b.y); }
__device__ __forceinline__ float2 cmul(float2 a, float2 b) {
    return make_float2(fmaf(a.x, b.x, -a.y * b.y), fmaf(a.x, b.y, a.y * b.x));
}
template <int DIR>
__device__ __forceinline__ float2 rotI(float2 z) {
    return (DIR < 0) ? make_float2(z.y, -z.x) : make_float2(-z.y, z.x);
}
template <int DIR>
__device__ __forceinline__ float2 cmulc(float2 z, float cr, float ci_fwd) {
    float ci = (DIR < 0) ? ci_fwd : -ci_fwd;
    return cmul(z, make_float2(cr, ci));
}
template <int DIR>
__device__ __forceinline__ float2 mulW2(float2 z) {
    const float H = 0.70710678118654752440f;
    return (DIR < 0) ? make_float2(H * (z.x + z.y), H * (z.y - z.x))
                     : make_float2(H * (z.x - z.y), H * (z.x + z.y));
}
template <int DIR>
__device__ __forceinline__ float2 mulW6(float2 z) {
    const float H = 0.70710678118654752440f;
    return (DIR < 0) ? make_float2(H * (z.y - z.x), -H * (z.x + z.y))
                     : make_float2(-H * (z.x + z.y), H * (z.x - z.y));
}

template <int DIR>
__device__ __forceinline__ void dft4(float2& a, float2& b, float2& c, float2& d) {
    float2 t0 = cadd(a, c), t1 = csub(a, c);
    float2 t2 = cadd(b, d), t3 = rotI<DIR>(csub(b, d));
    a = cadd(t0, t2);
    b = cadd(t1, t3);
    c = csub(t0, t2);
    d = csub(t1, t3);
}

#define OUT(q) ((((q) & 3) << 2) | ((q) >> 2))

template <int DIR>
__device__ __forceinline__ void dft16(float2 v[16]) {
    const float C1 = 0.92387953251128675613f;
    const float S1 = 0.38268343236508977173f;
    dft4<DIR>(v[0], v[4], v[8],  v[12]);
    dft4<DIR>(v[1], v[5], v[9],  v[13]);
    dft4<DIR>(v[2], v[6], v[10], v[14]);
    dft4<DIR>(v[3], v[7], v[11], v[15]);
    v[5]  = cmulc<DIR>(v[5],  C1, -S1);
    v[6]  = mulW2<DIR>(v[6]);
    v[7]  = cmulc<DIR>(v[7],  S1, -C1);
    v[9]  = mulW2<DIR>(v[9]);
    v[10] = rotI<DIR>(v[10]);
    v[11] = mulW6<DIR>(v[11]);
    v[13] = cmulc<DIR>(v[13], S1, -C1);
    v[14] = mulW6<DIR>(v[14]);
    v[15] = cmulc<DIR>(v[15], -C1, S1);
    dft4<DIR>(v[0],  v[1],  v[2],  v[3]);
    dft4<DIR>(v[4],  v[5],  v[6],  v[7]);
    dft4<DIR>(v[8],  v[9],  v[10], v[11]);
    dft4<DIR>(v[12], v[13], v[14], v[15]);
}

// v[r] *= exp(i*theta*r), r = 1..15 — independent MUFU sincos per twiddle
__device__ __forceinline__ void twiddle_ladder(float2 v[16], float theta) {
#pragma unroll
    for (int r = 1; r < 16; r++) {
        float s, c;
        __sincosf(theta * (float)r, &s, &c);
        v[r] = cmul(v[r], make_float2(c, s));
    }
}

// ---- per-row stage pieces (read+compute separated from write) ----

// stage 0: gmem + A -> dft16 -> regs
__device__ __forceinline__ void s0_read(float2 v[16], const float2* __restrict__ x,
                                        const float2* __restrict__ A, size_t base, int i) {
#pragma unroll
    for (int r = 0; r < 16; r++) {
        int c = i + NT * r;
        float2 xv = x[base + c];
        float2 a = A[c];
        v[r] = make_float2(a.x * xv.x, a.y * xv.y);
    }
    dft16<-1>(v);
}
__device__ __forceinline__ void blk_write(float2* sm, int i, float2 v[16]) {
#pragma unroll
    for (int q = 0; q < 16; q++) sm[PAD(16 * i + q)] = v[OUT(q)];
}

// mid stage (S=16): read + compute
template <int DIR>
__device__ __forceinline__ void mid_read(float2 v[16], const float2* sm, int i) {
#pragma unroll
    for (int r = 0; r < 16; r++) v[r] = sm[PAD(i + NT * r)];
    int k = i & 15;
    float theta = ((DIR < 0) ? -6.283185307179586f : 6.283185307179586f)
                  * (float)k / 256.0f;
    twiddle_ladder(v, theta);
    dft16<DIR>(v);
}
template <int DIR>
__device__ __forceinline__ void mid_write(float2* sm, int i, float2 v[16]) {
    int k = i & 15;
    int j = ((i & ~15) << 4) + k;
#pragma unroll
    for (int q = 0; q < 16; q++) sm[PAD(j + q * 16)] = v[OUT(q)];
}

// junction: fwd stage 2 + D scale + inv stage 0 (all regs)
__device__ __forceinline__ void jct_read(float2 g[16], const float2* sm,
                                         const float2* __restrict__ D, int i) {
    float2 u[16];
#pragma unroll
    for (int r = 0; r < 16; r++) u[r] = sm[PAD(i + NT * r)];
    twiddle_ladder(u, -6.283185307179586f * (float)i / (float)FFT_N);
    dft16<-1>(u);
    const float invN = 1.0f / (float)FFT_N;
#pragma unroll
    for (int r = 0; r < 16; r++) {
        float2 fv = u[OUT(r)];
        float2 d = D[i + NT * r];
        g[r] = make_float2(d.x * fv.x * invN, d.y * fv.y * invN);
    }
    dft16<1>(g);
}

// final stage: read + compute + gmem store
__device__ __forceinline__ void fin_row(const float2* sm, float2* __restrict__ out,
                                        size_t base, int i) {
    float2 u[16];
#pragma unroll
    for (int r = 0; r < 16; r++) u[r] = sm[PAD(i + NT * r)];
    twiddle_ladder(u, 6.283185307179586f * (float)i / (float)FFT_N);
    dft16<1>(u);
#pragma unroll
    for (int q = 0; q < 16; q++) out[base + i + NT * q] = u[OUT(q)];
}

extern __shared__ float2 smbuf[];   // [2][SMEM_E]: smA, smB

__global__ void __launch_bounds__(NT, 3)
afdf16d_kernel(const float2* __restrict__ x, const float2* __restrict__ A,
               const float2* __restrict__ D, float2* __restrict__ out, int rows) {
    float2* smA = smbuf;
    float2* smB = smbuf + SMEM_E;
    const int i = threadIdx.x;

    const int rowA = 2 * blockIdx.x;
    const int rowB_real = 2 * blockIdx.x + 1;
    const int rowB = (rowB_real < rows) ? rowB_real : rowA;  // degenerate duplicate if odd
    const size_t baseA = (size_t)rowA * FFT_N;
    const size_t baseB = (size_t)rowB * FFT_N;

    float2 v[16];

    // ---- stage 0: both rows, one sync ----
    s0_read(v, x, A, baseA, i);
    blk_write(smA, i, v);
    s0_read(v, x, A, baseB, i);
    blk_write(smB, i, v);
    __syncthreads();

    // ---- fwd stage 1 (S=16), interleaved ----
    mid_read<-1>(v, smA, i);
    __syncthreads();
    mid_write<-1>(smA, i, v);
    mid_read<-1>(v, smB, i);
    __syncthreads();
    mid_write<-1>(smB, i, v);

    // ---- junction (fwd s2 + D + inv s0), interleaved ----
    jct_read(v, smA, D, i);        // smA writes (s1) done: covered by sync above? NO —
                                   // s1-writeB happened after last sync; but jct reads smA,
                                   // whose writes precede the sync before s1-readB.  OK.
    __syncthreads();               // all smA reads (this stage) complete
    blk_write(smA, i, v);
    jct_read(v, smB, D, i);        // smB s1-writes separated from these reads by sync above
    __syncthreads();
    blk_write(smB, i, v);

    // ---- inv stage 1 (S=16), interleaved ----
    mid_read<1>(v, smA, i);        // smA junction-writes precede the last sync ✓
    __syncthreads();
    mid_write<1>(smA, i, v);
    mid_read<1>(v, smB, i);        // smB junction-writes precede the sync just above ✓
    __syncthreads();
    mid_write<1>(smB, i, v);
    __syncthreads();               // cover smB trailing writes before final reads

    // ---- final stage (inv s2) -> gmem, both rows ----
    fin_row(smA, out, baseA, i);
    if (rowB_real < rows) fin_row(smB, out, baseB, i);
}

extern "C" void kernel_launch(void* const* d_in, const int* in_sizes, int n_in,
                              void* d_out, int out_size) {
    const float2* x = (const float2*)d_in[0];
    const float2* A = (const float2*)d_in[1];
    const float2* D = (const float2*)d_in[2];
    float2* out = (float2*)d_out;

    int rows = in_sizes[0] / (FFT_N * 2);   // (B, C, 2) float32 -> B rows
    int grid = (rows + 1) / 2;

    const int smem_bytes = 2 * SMEM_E * sizeof(float2);  // 69632 B
    cudaFuncSetAttribute(afdf16d_kernel, cudaFuncAttributeMaxDynamicSharedMemorySize, smem_bytes);
    afdf16d_kernel<<<grid, NT, smem_bytes>>>(x, A, D, out, rows);
}